// round 1
// baseline (speedup 1.0000x reference)
#include <cuda_runtime.h>
#include <math.h>

// ---------------- problem constants ----------------
#define NN      20000          // nodes
#define EE      160000         // directed input edges
#define ETOT    (2*EE + NN)    // undirected + self loops = 340000
#define FF      128
#define HH      4
#define CC1     128
#define D1      (HH*CC1)       // 512
#define CC2     256
#define GG      64
#define NCLS    10

// ---------------- device scratch (static, no allocation) ----------------
__device__ float g_h1[NN * D1];       // x @ W1
__device__ float g_out1[NN * D1];     // relu(GAT1)
__device__ float g_h2[NN * CC2];      // out1 @ W2
__device__ float g_out2[NN * CC2];    // GAT2
__device__ float g_asrc1[NN * HH];
__device__ float g_adst1[NN * HH];
__device__ float g_asrc2[NN];
__device__ float g_adst2[NN];
__device__ float g_alpha1[ETOT * HH];
__device__ float g_alpha2[ETOT];
__device__ int   g_deg[NN];
__device__ int   g_rowptr[NN + 1];
__device__ int   g_wp[NN];
__device__ int   g_col[ETOT];
__device__ int   g_bsums[32];
__device__ int   g_starts[GG + 1];
__device__ float g_pool[GG * CC2];

// ---------------- CSR build ----------------
__global__ void k_init_deg(int n) {
    int i = blockIdx.x * blockDim.x + threadIdx.x;
    if (i < n) g_deg[i] = 1;  // self loop
}

__global__ void k_count_deg(const int* __restrict__ ei, int E) {
    int j = blockIdx.x * blockDim.x + threadIdx.x;
    if (j < E) {
        atomicAdd(&g_deg[ei[j]], 1);      // reverse edge into src
        atomicAdd(&g_deg[ei[E + j]], 1);  // forward edge into dst
    }
}

__global__ void k_scan_block(int n) {
    __shared__ int s[1024];
    int i = blockIdx.x * 1024 + threadIdx.x;
    int v = (i < n) ? g_deg[i] : 0;
    s[threadIdx.x] = v;
    __syncthreads();
    for (int off = 1; off < 1024; off <<= 1) {
        int x = (threadIdx.x >= off) ? s[threadIdx.x - off] : 0;
        __syncthreads();
        s[threadIdx.x] += x;
        __syncthreads();
    }
    if (i < n) g_rowptr[i] = s[threadIdx.x] - v;  // exclusive within block
    if (threadIdx.x == 1023) g_bsums[blockIdx.x] = s[1023];
}

__global__ void k_scan_bsums(int nb, int n) {
    if (threadIdx.x == 0 && blockIdx.x == 0) {
        int run = 0;
        for (int b = 0; b < nb; b++) { int t = g_bsums[b]; g_bsums[b] = run; run += t; }
        g_rowptr[n] = run;
    }
}

__global__ void k_scan_add(int n) {
    int i = blockIdx.x * blockDim.x + threadIdx.x;
    if (i < n) {
        int v = g_rowptr[i] + g_bsums[i >> 10];
        g_rowptr[i] = v;
        g_wp[i] = v;
    }
}

__global__ void k_scatter(const int* __restrict__ ei, int E, int n) {
    int j = blockIdx.x * blockDim.x + threadIdx.x;
    if (j < E) {
        int s = ei[j], d = ei[E + j];
        g_col[atomicAdd(&g_wp[d], 1)] = s;   // (s -> d)
        g_col[atomicAdd(&g_wp[s], 1)] = d;   // (d -> s)
    } else if (j < E + n) {
        int i = j - E;
        g_col[atomicAdd(&g_wp[i], 1)] = i;   // self loop
    }
}

// ---------------- SGEMM: C[M,N] = A[M,K] @ B[K,N], row-major, N%128==0, K%16==0 ----------------
#define BM 128
#define BN 128
#define BK 16
__global__ __launch_bounds__(256) void k_sgemm(const float* __restrict__ A,
                                               const float* __restrict__ B,
                                               float* __restrict__ C,
                                               int M, int N, int K) {
    __shared__ float As[BK][BM];
    __shared__ float Bs[BK][BN];
    int tid = threadIdx.x;
    int brow = blockIdx.y, bcol = blockIdx.x;
    int tx = tid & 15, ty = tid >> 4;
    float acc[8][8];
#pragma unroll
    for (int i = 0; i < 8; i++)
#pragma unroll
        for (int j = 0; j < 8; j++) acc[i][j] = 0.f;

    for (int k0 = 0; k0 < K; k0 += BK) {
        // load A tile (BM x BK), transpose to As[k][m]
#pragma unroll
        for (int li = 0; li < 2; li++) {
            int q = tid + li * 256;          // float4 index 0..511
            int row = q >> 2;
            int kk = (q & 3) << 2;
            int grow = brow * BM + row;
            float4 v = make_float4(0.f, 0.f, 0.f, 0.f);
            if (grow < M) v = *(const float4*)&A[(size_t)grow * K + k0 + kk];
            As[kk + 0][row] = v.x;
            As[kk + 1][row] = v.y;
            As[kk + 2][row] = v.z;
            As[kk + 3][row] = v.w;
        }
        // load B tile (BK x BN)
#pragma unroll
        for (int li = 0; li < 2; li++) {
            int q = tid + li * 256;
            int kr = q >> 5;
            int nc = (q & 31) << 2;
            float4 v = *(const float4*)&B[(size_t)(k0 + kr) * N + bcol * BN + nc];
            *(float4*)&Bs[kr][nc] = v;
        }
        __syncthreads();
#pragma unroll
        for (int k = 0; k < BK; k++) {
            float4 a0 = *(float4*)&As[k][ty * 8];
            float4 a1 = *(float4*)&As[k][ty * 8 + 4];
            float4 b0 = *(float4*)&Bs[k][tx * 8];
            float4 b1 = *(float4*)&Bs[k][tx * 8 + 4];
            float ra[8] = {a0.x, a0.y, a0.z, a0.w, a1.x, a1.y, a1.z, a1.w};
            float rb[8] = {b0.x, b0.y, b0.z, b0.w, b1.x, b1.y, b1.z, b1.w};
#pragma unroll
            for (int i = 0; i < 8; i++)
#pragma unroll
                for (int j = 0; j < 8; j++) acc[i][j] += ra[i] * rb[j];
        }
        __syncthreads();
    }
#pragma unroll
    for (int i = 0; i < 8; i++) {
        int r = brow * BM + ty * 8 + i;
        if (r < M) {
            float* cp = &C[(size_t)r * N + bcol * BN + tx * 8];
            *(float4*)cp = make_float4(acc[i][0], acc[i][1], acc[i][2], acc[i][3]);
            *(float4*)(cp + 4) = make_float4(acc[i][4], acc[i][5], acc[i][6], acc[i][7]);
        }
    }
}

// ---------------- attention dots ----------------
// layer1: h [N,512] (=[N,H=4,C=128]), att vectors [512]; block(128) per node, warp w = head w
__global__ void k_attdot1(const float* __restrict__ h, const float* __restrict__ as_,
                          const float* __restrict__ ad_, int n) {
    int nid = blockIdx.x;
    int t = threadIdx.x, w = t >> 5, lane = t & 31;
    float4 v = *(const float4*)&h[(size_t)nid * D1 + t * 4];
    float4 a = *(const float4*)&as_[t * 4];
    float4 b = *(const float4*)&ad_[t * 4];
    float ps = v.x * a.x + v.y * a.y + v.z * a.z + v.w * a.w;
    float pd = v.x * b.x + v.y * b.y + v.z * b.z + v.w * b.w;
#pragma unroll
    for (int o = 16; o > 0; o >>= 1) {
        ps += __shfl_xor_sync(0xffffffffu, ps, o);
        pd += __shfl_xor_sync(0xffffffffu, pd, o);
    }
    if (lane == 0) {
        g_asrc1[nid * HH + w] = ps;
        g_adst1[nid * HH + w] = pd;
    }
}

// layer2: h [N,256], H=1; warp per node
__global__ void k_attdot2(const float* __restrict__ h, const float* __restrict__ as_,
                          const float* __restrict__ ad_, int n) {
    int warp = (blockIdx.x * blockDim.x + threadIdx.x) >> 5;
    int lane = threadIdx.x & 31;
    if (warp >= n) return;
    const float* hr = h + (size_t)warp * CC2;
    float4 v0 = *(const float4*)&hr[lane * 8];
    float4 v1 = *(const float4*)&hr[lane * 8 + 4];
    float4 a0 = *(const float4*)&as_[lane * 8];
    float4 a1 = *(const float4*)&as_[lane * 8 + 4];
    float4 b0 = *(const float4*)&ad_[lane * 8];
    float4 b1 = *(const float4*)&ad_[lane * 8 + 4];
    float ps = v0.x * a0.x + v0.y * a0.y + v0.z * a0.z + v0.w * a0.w +
               v1.x * a1.x + v1.y * a1.y + v1.z * a1.z + v1.w * a1.w;
    float pd = v0.x * b0.x + v0.y * b0.y + v0.z * b0.z + v0.w * b0.w +
               v1.x * b1.x + v1.y * b1.y + v1.z * b1.z + v1.w * b1.w;
#pragma unroll
    for (int o = 16; o > 0; o >>= 1) {
        ps += __shfl_xor_sync(0xffffffffu, ps, o);
        pd += __shfl_xor_sync(0xffffffffu, pd, o);
    }
    if (lane == 0) {
        g_asrc2[warp] = ps;
        g_adst2[warp] = pd;
    }
}

// ---------------- edge softmax (per dst node, warp-per-node, atomic-free) ----------------
template <int H>
__global__ void k_edge_softmax(const float* __restrict__ asrc, const float* __restrict__ adst,
                               float* __restrict__ alpha, int n) {
    int d = (blockIdx.x * blockDim.x + threadIdx.x) >> 5;
    int lane = threadIdx.x & 31;
    if (d >= n) return;
    int beg = g_rowptr[d], end = g_rowptr[d + 1];
    float ad[H];
#pragma unroll
    for (int h = 0; h < H; h++) ad[h] = adst[d * H + h];
    float mx[H];
#pragma unroll
    for (int h = 0; h < H; h++) mx[h] = -1e30f;
    for (int k = beg + lane; k < end; k += 32) {
        int s = g_col[k];
#pragma unroll
        for (int h = 0; h < H; h++) {
            float e = asrc[s * H + h] + ad[h];
            e = (e > 0.f) ? e : 0.2f * e;
            mx[h] = fmaxf(mx[h], e);
        }
    }
#pragma unroll
    for (int o = 16; o > 0; o >>= 1)
#pragma unroll
        for (int h = 0; h < H; h++) mx[h] = fmaxf(mx[h], __shfl_xor_sync(0xffffffffu, mx[h], o));
    float sm[H];
#pragma unroll
    for (int h = 0; h < H; h++) sm[h] = 0.f;
    for (int k = beg + lane; k < end; k += 32) {
        int s = g_col[k];
#pragma unroll
        for (int h = 0; h < H; h++) {
            float e = asrc[s * H + h] + ad[h];
            e = (e > 0.f) ? e : 0.2f * e;
            float ee = __expf(e - mx[h]);
            alpha[k * H + h] = ee;
            sm[h] += ee;
        }
    }
#pragma unroll
    for (int o = 16; o > 0; o >>= 1)
#pragma unroll
        for (int h = 0; h < H; h++) sm[h] += __shfl_xor_sync(0xffffffffu, sm[h], o);
    float inv[H];
#pragma unroll
    for (int h = 0; h < H; h++) inv[h] = 1.f / sm[h];
    for (int k = beg + lane; k < end; k += 32) {
#pragma unroll
        for (int h = 0; h < H; h++) alpha[k * H + h] *= inv[h];
    }
}

// ---------------- aggregation ----------------
// layer1: block(128) per dst node; thread t covers channels 4t..4t+3; head = t/32; relu + bias
__global__ void k_aggregate1(const float* __restrict__ h, const float* __restrict__ bias,
                             float* __restrict__ out, int n) {
    int d = blockIdx.x;
    int t = threadIdx.x, w = t >> 5;
    int beg = g_rowptr[d], end = g_rowptr[d + 1];
    float ax = 0.f, ay = 0.f, az = 0.f, aw = 0.f;
    for (int k = beg; k < end; k++) {
        int s = g_col[k];                  // broadcast load
        float a = g_alpha1[k * HH + w];    // broadcast per warp
        float4 hv = *(const float4*)&h[(size_t)s * D1 + t * 4];
        ax += hv.x * a; ay += hv.y * a; az += hv.z * a; aw += hv.w * a;
    }
    float4 b = *(const float4*)&bias[t * 4];
    float4 r = make_float4(fmaxf(ax + b.x, 0.f), fmaxf(ay + b.y, 0.f),
                           fmaxf(az + b.z, 0.f), fmaxf(aw + b.w, 0.f));
    *(float4*)&out[(size_t)d * D1 + t * 4] = r;
}

// layer2: block(64) per dst node; channels 4t..4t+3 of 256; bias, no relu
__global__ void k_aggregate2(const float* __restrict__ h, const float* __restrict__ bias,
                             float* __restrict__ out, int n) {
    int d = blockIdx.x;
    int t = threadIdx.x;
    int beg = g_rowptr[d], end = g_rowptr[d + 1];
    float ax = 0.f, ay = 0.f, az = 0.f, aw = 0.f;
    for (int k = beg; k < end; k++) {
        int s = g_col[k];
        float a = g_alpha2[k];
        float4 hv = *(const float4*)&h[(size_t)s * CC2 + t * 4];
        ax += hv.x * a; ay += hv.y * a; az += hv.z * a; aw += hv.w * a;
    }
    float4 b = *(const float4*)&bias[t * 4];
    *(float4*)&out[(size_t)d * CC2 + t * 4] =
        make_float4(ax + b.x, ay + b.y, az + b.z, aw + b.w);
}

// ---------------- pooling + head ----------------
__global__ void k_starts(const int* __restrict__ batch, int n) {
    int i = blockIdx.x * blockDim.x + threadIdx.x;
    if (i < n) {
        if (i == 0) {
            g_starts[batch[0]] = 0;
            g_starts[GG] = n;
        } else if (batch[i] != batch[i - 1]) {
            g_starts[batch[i]] = i;
        }
    }
}

__global__ void k_pool(const float* __restrict__ x) {
    int g = blockIdx.x;
    int c = threadIdx.x;  // 256
    int beg = g_starts[g], end = g_starts[g + 1];
    float m = -1e30f;
    for (int i = beg; i < end; i++) m = fmaxf(m, x[(size_t)i * CC2 + c]);
    g_pool[g * CC2 + c] = m;
}

__global__ void k_head(const float* __restrict__ w1, const float* __restrict__ b1,
                       const float* __restrict__ w2, const float* __restrict__ b2,
                       float* __restrict__ out) {
    int g = blockIdx.x;
    int t = threadIdx.x;  // 64
    __shared__ float s1[64];
    __shared__ float logits[NCLS];
    float acc = b1[t];
    for (int k = 0; k < CC2; k++) acc += g_pool[g * CC2 + k] * w1[k * 64 + t];
    s1[t] = fmaxf(acc, 0.f);
    __syncthreads();
    if (t < NCLS) {
        float l = b2[t];
        for (int k = 0; k < 64; k++) l += s1[k] * w2[k * NCLS + t];
        logits[t] = l;
    }
    __syncthreads();
    if (t < NCLS) {
        float m = -1e30f;
        for (int j = 0; j < NCLS; j++) m = fmaxf(m, logits[j]);
        float se = 0.f;
        for (int j = 0; j < NCLS; j++) se += expf(logits[j] - m);
        out[g * NCLS + t] = logits[t] - m - logf(se);
    }
}

// ---------------- launch ----------------
extern "C" void kernel_launch(void* const* d_in, const int* in_sizes, int n_in,
                              void* d_out, int out_size) {
    const float* x        = (const float*)d_in[0];
    const int*   ei       = (const int*)d_in[1];
    const int*   batch    = (const int*)d_in[2];
    const float* W1       = (const float*)d_in[3];
    const float* att_src1 = (const float*)d_in[4];
    const float* att_dst1 = (const float*)d_in[5];
    const float* b1       = (const float*)d_in[6];
    const float* W2       = (const float*)d_in[7];
    const float* att_src2 = (const float*)d_in[8];
    const float* att_dst2 = (const float*)d_in[9];
    const float* b2       = (const float*)d_in[10];
    const float* fc1_w    = (const float*)d_in[11];
    const float* fc1_b    = (const float*)d_in[12];
    const float* fc2_w    = (const float*)d_in[13];
    const float* fc2_b    = (const float*)d_in[14];
    float* out = (float*)d_out;

    const int n = in_sizes[2];       // 20000
    const int E = in_sizes[1] / 2;   // 160000

    float *h1, *out1, *h2, *out2, *asrc1, *adst1, *asrc2, *adst2, *alpha1, *alpha2;
    cudaGetSymbolAddress((void**)&h1, g_h1);
    cudaGetSymbolAddress((void**)&out1, g_out1);
    cudaGetSymbolAddress((void**)&h2, g_h2);
    cudaGetSymbolAddress((void**)&out2, g_out2);
    cudaGetSymbolAddress((void**)&asrc1, g_asrc1);
    cudaGetSymbolAddress((void**)&adst1, g_adst1);
    cudaGetSymbolAddress((void**)&asrc2, g_asrc2);
    cudaGetSymbolAddress((void**)&adst2, g_adst2);
    cudaGetSymbolAddress((void**)&alpha1, g_alpha1);
    cudaGetSymbolAddress((void**)&alpha2, g_alpha2);

    // ---- CSR build ----
    k_init_deg<<<(n + 255) / 256, 256>>>(n);
    k_count_deg<<<(E + 255) / 256, 256>>>(ei, E);
    int nb = (n + 1023) / 1024;
    k_scan_block<<<nb, 1024>>>(n);
    k_scan_bsums<<<1, 32>>>(nb, n);
    k_scan_add<<<(n + 255) / 256, 256>>>(n);
    k_scatter<<<(E + n + 255) / 256, 256>>>(ei, E, n);

    // ---- layer 1 ----
    {
        dim3 grid(D1 / BN, (n + BM - 1) / BM);
        k_sgemm<<<grid, 256>>>(x, W1, h1, n, D1, FF);
    }
    k_attdot1<<<n, 128>>>(h1, att_src1, att_dst1, n);
    k_edge_softmax<HH><<<(n * 32 + 255) / 256, 256>>>(asrc1, adst1, alpha1, n);
    k_aggregate1<<<n, 128>>>(h1, b1, out1, n);

    // ---- layer 2 ----
    {
        dim3 grid(CC2 / BN, (n + BM - 1) / BM);
        k_sgemm<<<grid, 256>>>(out1, W2, h2, n, CC2, D1);
    }
    k_attdot2<<<(n * 32 + 255) / 256, 256>>>(h2, att_src2, att_dst2, n);
    k_edge_softmax<1><<<(n * 32 + 255) / 256, 256>>>(asrc2, adst2, alpha2, n);
    k_aggregate2<<<n, 64>>>(h2, b2, out2, n);

    // ---- pool + head ----
    k_starts<<<(n + 255) / 256, 256>>>(batch, n);
    k_pool<<<GG, CC2>>>(out2);
    k_head<<<GG, 64>>>(fc1_w, fc1_b, fc2_w, fc2_b, out);
}

// round 2
// speedup vs baseline: 1.6775x; 1.6775x over previous
#include <cuda_runtime.h>
#include <math.h>

// ---------------- problem constants ----------------
#define NN      20000          // nodes
#define EE      160000         // directed input edges
#define ETOT    (2*EE + NN)    // undirected + self loops = 340000
#define FF      128
#define HH      4
#define CC1     128
#define D1      (HH*CC1)       // 512
#define CC2     256
#define GG      64
#define NCLS    10

// ---------------- device scratch (static, no allocation) ----------------
__device__ float g_h1[NN * D1];       // x @ W1
__device__ float g_out1[NN * D1];     // relu(GAT1)
__device__ float g_h2[NN * CC2];      // out1 @ W2
__device__ float g_out2[NN * CC2];    // GAT2
__device__ float g_asrc1[NN * HH];
__device__ float g_adst1[NN * HH];
__device__ float g_asrc2[NN];
__device__ float g_adst2[NN];
__device__ float g_alpha1[ETOT * HH];
__device__ float g_alpha2[ETOT];
__device__ int   g_deg[NN];
__device__ int   g_rowptr[NN + 1];
__device__ int   g_wp[NN];
__device__ int   g_col[ETOT];
__device__ int   g_bsums[32];
__device__ int   g_starts[GG + 1];
__device__ float g_pool[GG * CC2];

// ---------------- CSR build ----------------
__global__ void k_init_deg(int n) {
    int i = blockIdx.x * blockDim.x + threadIdx.x;
    if (i < n) g_deg[i] = 1;  // self loop
}

__global__ void k_count_deg(const int* __restrict__ ei, int E) {
    int j = blockIdx.x * blockDim.x + threadIdx.x;
    if (j < E) {
        atomicAdd(&g_deg[ei[j]], 1);      // reverse edge into src
        atomicAdd(&g_deg[ei[E + j]], 1);  // forward edge into dst
    }
}

__global__ void k_scan_block(int n) {
    __shared__ int s[1024];
    int i = blockIdx.x * 1024 + threadIdx.x;
    int v = (i < n) ? g_deg[i] : 0;
    s[threadIdx.x] = v;
    __syncthreads();
    for (int off = 1; off < 1024; off <<= 1) {
        int x = (threadIdx.x >= off) ? s[threadIdx.x - off] : 0;
        __syncthreads();
        s[threadIdx.x] += x;
        __syncthreads();
    }
    if (i < n) g_rowptr[i] = s[threadIdx.x] - v;  // exclusive within block
    if (threadIdx.x == 1023) g_bsums[blockIdx.x] = s[1023];
}

// warp-parallel scan of per-block sums (nb <= 32)
__global__ void k_scan_bsums(int nb, int n) {
    int t = threadIdx.x;
    int v = (t < nb) ? g_bsums[t] : 0;
    int orig = v;
#pragma unroll
    for (int o = 1; o < 32; o <<= 1) {
        int x = __shfl_up_sync(0xffffffffu, v, o);
        if (t >= o) v += x;
    }
    if (t < nb) g_bsums[t] = v - orig;   // exclusive
    if (t == nb - 1) g_rowptr[n] = v;    // total
}

__global__ void k_scan_add(int n) {
    int i = blockIdx.x * blockDim.x + threadIdx.x;
    if (i < n) {
        int v = g_rowptr[i] + g_bsums[i >> 10];
        g_rowptr[i] = v;
        g_wp[i] = v;
    }
}

__global__ void k_scatter(const int* __restrict__ ei, int E, int n) {
    int j = blockIdx.x * blockDim.x + threadIdx.x;
    if (j < E) {
        int s = ei[j], d = ei[E + j];
        g_col[atomicAdd(&g_wp[d], 1)] = s;   // (s -> d)
        g_col[atomicAdd(&g_wp[s], 1)] = d;   // (d -> s)
    } else if (j < E + n) {
        int i = j - E;
        g_col[atomicAdd(&g_wp[i], 1)] = i;   // self loop
    }
}

// ---------------- tf32 tensor-core GEMM ----------------
// C[M,N] = A[M,K] @ B[K,N], row-major. N%128==0, K%32==0.
__device__ __forceinline__ unsigned f2tf32(float x) {
    unsigned r;
    asm("cvt.rna.tf32.f32 %0, %1;" : "=r"(r) : "f"(x));
    return r;
}

__device__ __forceinline__ void mma_tf32(float c[4], const unsigned a[4], const unsigned b[2]) {
    asm volatile(
        "mma.sync.aligned.m16n8k8.row.col.f32.tf32.tf32.f32 "
        "{%0,%1,%2,%3}, {%4,%5,%6,%7}, {%8,%9}, {%0,%1,%2,%3};"
        : "+f"(c[0]), "+f"(c[1]), "+f"(c[2]), "+f"(c[3])
        : "r"(a[0]), "r"(a[1]), "r"(a[2]), "r"(a[3]), "r"(b[0]), "r"(b[1]));
}

#define TBM 128
#define TBN 128
#define TBK 32
__global__ __launch_bounds__(256) void k_gemm_tf32(const float* __restrict__ A,
                                                   const float* __restrict__ B,
                                                   float* __restrict__ C,
                                                   int M, int N, int K) {
    __shared__ unsigned As[TBM][TBK + 4];   // stride 36 -> conflict-free frag loads
    __shared__ unsigned Bs[TBK][TBN + 4];   // stride 132 -> conflict-free frag loads
    int tid = threadIdx.x;
    int bm = blockIdx.y * TBM, bn = blockIdx.x * TBN;
    int w = tid >> 5, lane = tid & 31;
    int wy = w & 3, wx = w >> 2;            // warp tile: m = wy*32, n = wx*64
    int gid = lane >> 2, tig = lane & 3;

    float c[2][8][4];
#pragma unroll
    for (int mt = 0; mt < 2; mt++)
#pragma unroll
        for (int nt = 0; nt < 8; nt++)
#pragma unroll
            for (int r = 0; r < 4; r++) c[mt][nt][r] = 0.f;

    for (int k0 = 0; k0 < K; k0 += TBK) {
        // A tile: 128 x 32 floats = 1024 float4, 4 per thread
#pragma unroll
        for (int i = 0; i < 4; i++) {
            int q = tid + i * 256;
            int row = q >> 3;
            int kk = (q & 7) << 2;
            int gr = bm + row;
            float4 v = make_float4(0.f, 0.f, 0.f, 0.f);
            if (gr < M) v = *(const float4*)&A[(size_t)gr * K + k0 + kk];
            As[row][kk + 0] = f2tf32(v.x);
            As[row][kk + 1] = f2tf32(v.y);
            As[row][kk + 2] = f2tf32(v.z);
            As[row][kk + 3] = f2tf32(v.w);
        }
        // B tile: 32 x 128 floats = 1024 float4
#pragma unroll
        for (int i = 0; i < 4; i++) {
            int q = tid + i * 256;
            int kr = q >> 5;
            int nc = (q & 31) << 2;
            float4 v = *(const float4*)&B[(size_t)(k0 + kr) * N + bn + nc];
            Bs[kr][nc + 0] = f2tf32(v.x);
            Bs[kr][nc + 1] = f2tf32(v.y);
            Bs[kr][nc + 2] = f2tf32(v.z);
            Bs[kr][nc + 3] = f2tf32(v.w);
        }
        __syncthreads();
#pragma unroll
        for (int ks = 0; ks < 4; ks++) {
            int kb = ks * 8;
            unsigned af[2][4], bf[8][2];
#pragma unroll
            for (int mt = 0; mt < 2; mt++) {
                int r0 = wy * 32 + mt * 16;
                af[mt][0] = As[r0 + gid][kb + tig];
                af[mt][1] = As[r0 + gid + 8][kb + tig];
                af[mt][2] = As[r0 + gid][kb + tig + 4];
                af[mt][3] = As[r0 + gid + 8][kb + tig + 4];
            }
#pragma unroll
            for (int nt = 0; nt < 8; nt++) {
                int c0 = wx * 64 + nt * 8;
                bf[nt][0] = Bs[kb + tig][c0 + gid];
                bf[nt][1] = Bs[kb + tig + 4][c0 + gid];
            }
#pragma unroll
            for (int mt = 0; mt < 2; mt++)
#pragma unroll
                for (int nt = 0; nt < 8; nt++) mma_tf32(c[mt][nt], af[mt], bf[nt]);
        }
        __syncthreads();
    }
#pragma unroll
    for (int mt = 0; mt < 2; mt++) {
        int r0 = bm + wy * 32 + mt * 16 + gid;
#pragma unroll
        for (int nt = 0; nt < 8; nt++) {
            int cc = bn + wx * 64 + nt * 8 + 2 * tig;
            if (r0 < M)
                *(float2*)&C[(size_t)r0 * N + cc] = make_float2(c[mt][nt][0], c[mt][nt][1]);
            if (r0 + 8 < M)
                *(float2*)&C[(size_t)(r0 + 8) * N + cc] = make_float2(c[mt][nt][2], c[mt][nt][3]);
        }
    }
}

// ---------------- attention dots ----------------
__global__ void k_attdot1(const float* __restrict__ h, const float* __restrict__ as_,
                          const float* __restrict__ ad_, int n) {
    int nid = blockIdx.x;
    int t = threadIdx.x, w = t >> 5, lane = t & 31;
    float4 v = *(const float4*)&h[(size_t)nid * D1 + t * 4];
    float4 a = *(const float4*)&as_[t * 4];
    float4 b = *(const float4*)&ad_[t * 4];
    float ps = v.x * a.x + v.y * a.y + v.z * a.z + v.w * a.w;
    float pd = v.x * b.x + v.y * b.y + v.z * b.z + v.w * b.w;
#pragma unroll
    for (int o = 16; o > 0; o >>= 1) {
        ps += __shfl_xor_sync(0xffffffffu, ps, o);
        pd += __shfl_xor_sync(0xffffffffu, pd, o);
    }
    if (lane == 0) {
        g_asrc1[nid * HH + w] = ps;
        g_adst1[nid * HH + w] = pd;
    }
}

__global__ void k_attdot2(const float* __restrict__ h, const float* __restrict__ as_,
                          const float* __restrict__ ad_, int n) {
    int warp = (blockIdx.x * blockDim.x + threadIdx.x) >> 5;
    int lane = threadIdx.x & 31;
    if (warp >= n) return;
    const float* hr = h + (size_t)warp * CC2;
    float4 v0 = *(const float4*)&hr[lane * 8];
    float4 v1 = *(const float4*)&hr[lane * 8 + 4];
    float4 a0 = *(const float4*)&as_[lane * 8];
    float4 a1 = *(const float4*)&as_[lane * 8 + 4];
    float4 b0 = *(const float4*)&ad_[lane * 8];
    float4 b1 = *(const float4*)&ad_[lane * 8 + 4];
    float ps = v0.x * a0.x + v0.y * a0.y + v0.z * a0.z + v0.w * a0.w +
               v1.x * a1.x + v1.y * a1.y + v1.z * a1.z + v1.w * a1.w;
    float pd = v0.x * b0.x + v0.y * b0.y + v0.z * b0.z + v0.w * b0.w +
               v1.x * b1.x + v1.y * b1.y + v1.z * b1.z + v1.w * b1.w;
#pragma unroll
    for (int o = 16; o > 0; o >>= 1) {
        ps += __shfl_xor_sync(0xffffffffu, ps, o);
        pd += __shfl_xor_sync(0xffffffffu, pd, o);
    }
    if (lane == 0) {
        g_asrc2[warp] = ps;
        g_adst2[warp] = pd;
    }
}

// ---------------- edge softmax (per dst node, warp-per-node, atomic-free) ----------------
template <int H>
__global__ void k_edge_softmax(const float* __restrict__ asrc, const float* __restrict__ adst,
                               float* __restrict__ alpha, int n) {
    int d = (blockIdx.x * blockDim.x + threadIdx.x) >> 5;
    int lane = threadIdx.x & 31;
    if (d >= n) return;
    int beg = g_rowptr[d], end = g_rowptr[d + 1];
    float ad[H];
#pragma unroll
    for (int h = 0; h < H; h++) ad[h] = adst[d * H + h];
    float mx[H];
#pragma unroll
    for (int h = 0; h < H; h++) mx[h] = -1e30f;
    for (int k = beg + lane; k < end; k += 32) {
        int s = g_col[k];
#pragma unroll
        for (int h = 0; h < H; h++) {
            float e = asrc[s * H + h] + ad[h];
            e = (e > 0.f) ? e : 0.2f * e;
            mx[h] = fmaxf(mx[h], e);
        }
    }
#pragma unroll
    for (int o = 16; o > 0; o >>= 1)
#pragma unroll
        for (int h = 0; h < H; h++) mx[h] = fmaxf(mx[h], __shfl_xor_sync(0xffffffffu, mx[h], o));
    float sm[H];
#pragma unroll
    for (int h = 0; h < H; h++) sm[h] = 0.f;
    for (int k = beg + lane; k < end; k += 32) {
        int s = g_col[k];
#pragma unroll
        for (int h = 0; h < H; h++) {
            float e = asrc[s * H + h] + ad[h];
            e = (e > 0.f) ? e : 0.2f * e;
            float ee = __expf(e - mx[h]);
            alpha[k * H + h] = ee;
            sm[h] += ee;
        }
    }
#pragma unroll
    for (int o = 16; o > 0; o >>= 1)
#pragma unroll
        for (int h = 0; h < H; h++) sm[h] += __shfl_xor_sync(0xffffffffu, sm[h], o);
    float inv[H];
#pragma unroll
    for (int h = 0; h < H; h++) inv[h] = 1.f / sm[h];
    for (int k = beg + lane; k < end; k += 32) {
#pragma unroll
        for (int h = 0; h < H; h++) alpha[k * H + h] *= inv[h];
    }
}

// ---------------- aggregation ----------------
__global__ void k_aggregate1(const float* __restrict__ h, const float* __restrict__ bias,
                             float* __restrict__ out, int n) {
    int d = blockIdx.x;
    int t = threadIdx.x, w = t >> 5;
    int beg = g_rowptr[d], end = g_rowptr[d + 1];
    float ax = 0.f, ay = 0.f, az = 0.f, aw = 0.f;
    for (int k = beg; k < end; k++) {
        int s = g_col[k];
        float a = g_alpha1[k * HH + w];
        float4 hv = *(const float4*)&h[(size_t)s * D1 + t * 4];
        ax += hv.x * a; ay += hv.y * a; az += hv.z * a; aw += hv.w * a;
    }
    float4 b = *(const float4*)&bias[t * 4];
    float4 r = make_float4(fmaxf(ax + b.x, 0.f), fmaxf(ay + b.y, 0.f),
                           fmaxf(az + b.z, 0.f), fmaxf(aw + b.w, 0.f));
    *(float4*)&out[(size_t)d * D1 + t * 4] = r;
}

__global__ void k_aggregate2(const float* __restrict__ h, const float* __restrict__ bias,
                             float* __restrict__ out, int n) {
    int d = blockIdx.x;
    int t = threadIdx.x;
    int beg = g_rowptr[d], end = g_rowptr[d + 1];
    float ax = 0.f, ay = 0.f, az = 0.f, aw = 0.f;
    for (int k = beg; k < end; k++) {
        int s = g_col[k];
        float a = g_alpha2[k];
        float4 hv = *(const float4*)&h[(size_t)s * CC2 + t * 4];
        ax += hv.x * a; ay += hv.y * a; az += hv.z * a; aw += hv.w * a;
    }
    float4 b = *(const float4*)&bias[t * 4];
    *(float4*)&out[(size_t)d * CC2 + t * 4] =
        make_float4(ax + b.x, ay + b.y, az + b.z, aw + b.w);
}

// ---------------- pooling + head ----------------
__global__ void k_starts(const int* __restrict__ batch, int n) {
    int i = blockIdx.x * blockDim.x + threadIdx.x;
    if (i < n) {
        if (i == 0) {
            g_starts[batch[0]] = 0;
            g_starts[GG] = n;
        } else if (batch[i] != batch[i - 1]) {
            g_starts[batch[i]] = i;
        }
    }
}

__global__ void k_pool(const float* __restrict__ x) {
    int g = blockIdx.x;
    int c = threadIdx.x;  // 256
    int beg = g_starts[g], end = g_starts[g + 1];
    float m = -1e30f;
    for (int i = beg; i < end; i++) m = fmaxf(m, x[(size_t)i * CC2 + c]);
    g_pool[g * CC2 + c] = m;
}

__global__ void k_head(const float* __restrict__ w1, const float* __restrict__ b1,
                       const float* __restrict__ w2, const float* __restrict__ b2,
                       float* __restrict__ out) {
    int g = blockIdx.x;
    int t = threadIdx.x;  // 64
    __shared__ float s1[64];
    __shared__ float logits[NCLS];
    float acc = b1[t];
    for (int k = 0; k < CC2; k++) acc += g_pool[g * CC2 + k] * w1[k * 64 + t];
    s1[t] = fmaxf(acc, 0.f);
    __syncthreads();
    if (t < NCLS) {
        float l = b2[t];
        for (int k = 0; k < 64; k++) l += s1[k] * w2[k * NCLS + t];
        logits[t] = l;
    }
    __syncthreads();
    if (t < NCLS) {
        float m = -1e30f;
        for (int j = 0; j < NCLS; j++) m = fmaxf(m, logits[j]);
        float se = 0.f;
        for (int j = 0; j < NCLS; j++) se += expf(logits[j] - m);
        out[g * NCLS + t] = logits[t] - m - logf(se);
    }
}

// ---------------- launch ----------------
extern "C" void kernel_launch(void* const* d_in, const int* in_sizes, int n_in,
                              void* d_out, int out_size) {
    const float* x        = (const float*)d_in[0];
    const int*   ei       = (const int*)d_in[1];
    const int*   batch    = (const int*)d_in[2];
    const float* W1       = (const float*)d_in[3];
    const float* att_src1 = (const float*)d_in[4];
    const float* att_dst1 = (const float*)d_in[5];
    const float* b1       = (const float*)d_in[6];
    const float* W2       = (const float*)d_in[7];
    const float* att_src2 = (const float*)d_in[8];
    const float* att_dst2 = (const float*)d_in[9];
    const float* b2       = (const float*)d_in[10];
    const float* fc1_w    = (const float*)d_in[11];
    const float* fc1_b    = (const float*)d_in[12];
    const float* fc2_w    = (const float*)d_in[13];
    const float* fc2_b    = (const float*)d_in[14];
    float* out = (float*)d_out;

    const int n = in_sizes[2];       // 20000
    const int E = in_sizes[1] / 2;   // 160000

    float *h1, *out1, *h2, *out2, *asrc1, *adst1, *asrc2, *adst2, *alpha1, *alpha2;
    cudaGetSymbolAddress((void**)&h1, g_h1);
    cudaGetSymbolAddress((void**)&out1, g_out1);
    cudaGetSymbolAddress((void**)&h2, g_h2);
    cudaGetSymbolAddress((void**)&out2, g_out2);
    cudaGetSymbolAddress((void**)&asrc1, g_asrc1);
    cudaGetSymbolAddress((void**)&adst1, g_adst1);
    cudaGetSymbolAddress((void**)&asrc2, g_asrc2);
    cudaGetSymbolAddress((void**)&adst2, g_adst2);
    cudaGetSymbolAddress((void**)&alpha1, g_alpha1);
    cudaGetSymbolAddress((void**)&alpha2, g_alpha2);

    // ---- CSR build ----
    k_init_deg<<<(n + 255) / 256, 256>>>(n);
    k_count_deg<<<(E + 255) / 256, 256>>>(ei, E);
    int nb = (n + 1023) / 1024;
    k_scan_block<<<nb, 1024>>>(n);
    k_scan_bsums<<<1, 32>>>(nb, n);
    k_scan_add<<<(n + 255) / 256, 256>>>(n);
    k_scatter<<<(E + n + 255) / 256, 256>>>(ei, E, n);

    // ---- layer 1 ----
    {
        dim3 grid(D1 / TBN, (n + TBM - 1) / TBM);
        k_gemm_tf32<<<grid, 256>>>(x, W1, h1, n, D1, FF);
    }
    k_attdot1<<<n, 128>>>(h1, att_src1, att_dst1, n);
    k_edge_softmax<HH><<<(n * 32 + 255) / 256, 256>>>(asrc1, adst1, alpha1, n);
    k_aggregate1<<<n, 128>>>(h1, b1, out1, n);

    // ---- layer 2 ----
    {
        dim3 grid(CC2 / TBN, (n + TBM - 1) / TBM);
        k_gemm_tf32<<<grid, 256>>>(out1, W2, h2, n, CC2, D1);
    }
    k_attdot2<<<(n * 32 + 255) / 256, 256>>>(h2, att_src2, att_dst2, n);
    k_edge_softmax<1><<<(n * 32 + 255) / 256, 256>>>(asrc2, adst2, alpha2, n);
    k_aggregate2<<<n, 64>>>(h2, b2, out2, n);

    // ---- pool + head ----
    k_starts<<<(n + 255) / 256, 256>>>(batch, n);
    k_pool<<<GG, CC2>>>(out2);
    k_head<<<GG, 64>>>(fc1_w, fc1_b, fc2_w, fc2_b, out);
}

// round 4
// speedup vs baseline: 1.8255x; 1.0882x over previous
#include <cuda_runtime.h>
#include <math.h>
#include <stdint.h>

// ---------------- problem constants ----------------
#define NN      20000
#define EE      160000
#define ETOT    (2*EE + NN)
#define FF      128
#define HH      4
#define CC1     128
#define D1      (HH*CC1)       // 512
#define CC2     256
#define GG      64
#define NCLS    10

// ---------------- device scratch ----------------
__device__ float g_h1[NN * D1];
__device__ float g_out1[NN * D1];
__device__ float g_h2[NN * CC2];
__device__ float g_out2[NN * CC2];
__device__ float g_asrc1[NN * HH];
__device__ float g_adst1[NN * HH];
__device__ float g_asrc2[NN];
__device__ float g_adst2[NN];
__device__ int   g_deg[NN];
__device__ int   g_rowptr[NN + 1];
__device__ int   g_wp[NN];
__device__ int   g_col[ETOT];
__device__ int   g_bsums[32];
__device__ int   g_starts[GG + 1];

// ---------------- CSR build ----------------
__global__ void k_init(const int* __restrict__ batch, int n) {
    int i = blockIdx.x * blockDim.x + threadIdx.x;
    if (i < n) {
        g_deg[i] = 1;  // self loop
        if (i == 0) {
            g_starts[batch[0]] = 0;
            g_starts[GG] = n;
        } else if (batch[i] != batch[i - 1]) {
            g_starts[batch[i]] = i;
        }
    }
}

__global__ void k_count_deg(const int* __restrict__ ei, int E) {
    int j = blockIdx.x * blockDim.x + threadIdx.x;
    if (j < E) {
        atomicAdd(&g_deg[ei[j]], 1);
        atomicAdd(&g_deg[ei[E + j]], 1);
    }
}

__global__ void k_scan_block(int n) {
    __shared__ int s[1024];
    int i = blockIdx.x * 1024 + threadIdx.x;
    int v = (i < n) ? g_deg[i] : 0;
    s[threadIdx.x] = v;
    __syncthreads();
    for (int off = 1; off < 1024; off <<= 1) {
        int x = (threadIdx.x >= off) ? s[threadIdx.x - off] : 0;
        __syncthreads();
        s[threadIdx.x] += x;
        __syncthreads();
    }
    if (i < n) g_rowptr[i] = s[threadIdx.x] - v;
    if (threadIdx.x == 1023) g_bsums[blockIdx.x] = s[1023];
}

__global__ void k_scan_bsums(int nb, int n) {
    int t = threadIdx.x;
    int v = (t < nb) ? g_bsums[t] : 0;
    int orig = v;
#pragma unroll
    for (int o = 1; o < 32; o <<= 1) {
        int x = __shfl_up_sync(0xffffffffu, v, o);
        if (t >= o) v += x;
    }
    if (t < nb) g_bsums[t] = v - orig;
    if (t == nb - 1) g_rowptr[n] = v;
}

__global__ void k_scan_add(int n) {
    int i = blockIdx.x * blockDim.x + threadIdx.x;
    if (i < n) {
        int v = g_rowptr[i] + g_bsums[i >> 10];
        g_rowptr[i] = v;
        g_wp[i] = v;
    }
}

__global__ void k_scatter(const int* __restrict__ ei, int E, int n) {
    int j = blockIdx.x * blockDim.x + threadIdx.x;
    if (j < E) {
        int s = ei[j], d = ei[E + j];
        g_col[atomicAdd(&g_wp[d], 1)] = s;
        g_col[atomicAdd(&g_wp[s], 1)] = d;
    } else if (j < E + n) {
        int i = j - E;
        g_col[atomicAdd(&g_wp[i], 1)] = i;
    }
}

// ---------------- tf32 tensor-core GEMM (cp.async 2-stage) ----------------
__device__ __forceinline__ void mma_tf32(float c[4], const unsigned a[4], const unsigned b[2]) {
    asm volatile(
        "mma.sync.aligned.m16n8k8.row.col.f32.tf32.tf32.f32 "
        "{%0,%1,%2,%3}, {%4,%5,%6,%7}, {%8,%9}, {%0,%1,%2,%3};"
        : "+f"(c[0]), "+f"(c[1]), "+f"(c[2]), "+f"(c[3])
        : "r"(a[0]), "r"(a[1]), "r"(a[2]), "r"(a[3]), "r"(b[0]), "r"(b[1]));
}

__device__ __forceinline__ void cp16(uint32_t dst, const float* src, int szbytes) {
    asm volatile("cp.async.ca.shared.global [%0], [%1], 16, %2;\n"
                 :: "r"(dst), "l"(src), "r"(szbytes));
}

#define TBM 128
#define TBN 128
#define TBK 32
#define AS_STRIDE (TBK + 4)               // 36
#define BS_STRIDE (TBN + 4)               // 132
#define AS_SIZE (TBM * AS_STRIDE)         // 4608 floats
#define BS_SIZE (TBK * BS_STRIDE)         // 4224 floats
#define GEMM_SMEM_BYTES (2 * (AS_SIZE + BS_SIZE) * 4)  // 70656

__global__ __launch_bounds__(256) void k_gemm_tf32(const float* __restrict__ A,
                                                   const float* __restrict__ B,
                                                   float* __restrict__ C,
                                                   int M, int N, int K) {
    extern __shared__ float sm_[];
    float* As = sm_;                       // [2][AS_SIZE]
    float* Bs = sm_ + 2 * AS_SIZE;         // [2][BS_SIZE]
    uint32_t as_base = (uint32_t)__cvta_generic_to_shared(As);
    uint32_t bs_base = (uint32_t)__cvta_generic_to_shared(Bs);

    int tid = threadIdx.x;
    int bm = blockIdx.y * TBM, bn = blockIdx.x * TBN;
    int w = tid >> 5, lane = tid & 31;
    int wy = w & 3, wx = w >> 2;
    int gid = lane >> 2, tig = lane & 3;

    float c[2][8][4];
#pragma unroll
    for (int mt = 0; mt < 2; mt++)
#pragma unroll
        for (int nt = 0; nt < 8; nt++)
#pragma unroll
            for (int r = 0; r < 4; r++) c[mt][nt][r] = 0.f;

    const int KT = K / TBK;

    // tile loader
    auto load_tile = [&](int k0, int st) {
#pragma unroll
        for (int i = 0; i < 4; i++) {
            int q = tid + i * 256;
            int row = q >> 3;
            int kk = (q & 7) << 2;
            int gr = bm + row;
            uint32_t d = as_base + (uint32_t)(st * AS_SIZE + row * AS_STRIDE + kk) * 4u;
            cp16(d, &A[(size_t)gr * K + k0 + kk], (gr < M) ? 16 : 0);
        }
#pragma unroll
        for (int i = 0; i < 4; i++) {
            int q = tid + i * 256;
            int kr = q >> 5;
            int nc = (q & 31) << 2;
            uint32_t d = bs_base + (uint32_t)(st * BS_SIZE + kr * BS_STRIDE + nc) * 4u;
            cp16(d, &B[(size_t)(k0 + kr) * N + bn + nc], 16);
        }
        asm volatile("cp.async.commit_group;\n");
    };

    load_tile(0, 0);

    for (int it = 0; it < KT; it++) {
        if (it + 1 < KT) {
            load_tile((it + 1) * TBK, (it + 1) & 1);
            asm volatile("cp.async.wait_group 1;\n");
        } else {
            asm volatile("cp.async.wait_group 0;\n");
        }
        __syncthreads();

        const float* as = As + (it & 1) * AS_SIZE;
        const float* bsm = Bs + (it & 1) * BS_SIZE;
#pragma unroll
        for (int ks = 0; ks < 4; ks++) {
            int kb = ks * 8;
            unsigned af[2][4], bf[8][2];
#pragma unroll
            for (int mt = 0; mt < 2; mt++) {
                int r0 = wy * 32 + mt * 16;
                af[mt][0] = __float_as_uint(as[(r0 + gid) * AS_STRIDE + kb + tig]);
                af[mt][1] = __float_as_uint(as[(r0 + gid + 8) * AS_STRIDE + kb + tig]);
                af[mt][2] = __float_as_uint(as[(r0 + gid) * AS_STRIDE + kb + tig + 4]);
                af[mt][3] = __float_as_uint(as[(r0 + gid + 8) * AS_STRIDE + kb + tig + 4]);
            }
#pragma unroll
            for (int nt = 0; nt < 8; nt++) {
                int c0 = wx * 64 + nt * 8;
                bf[nt][0] = __float_as_uint(bsm[(kb + tig) * BS_STRIDE + c0 + gid]);
                bf[nt][1] = __float_as_uint(bsm[(kb + tig + 4) * BS_STRIDE + c0 + gid]);
            }
#pragma unroll
            for (int mt = 0; mt < 2; mt++)
#pragma unroll
                for (int nt = 0; nt < 8; nt++) mma_tf32(c[mt][nt], af[mt], bf[nt]);
        }
        __syncthreads();
    }

#pragma unroll
    for (int mt = 0; mt < 2; mt++) {
        int r0 = bm + wy * 32 + mt * 16 + gid;
#pragma unroll
        for (int nt = 0; nt < 8; nt++) {
            int cc = bn + wx * 64 + nt * 8 + 2 * tig;
            if (r0 < M)
                *(float2*)&C[(size_t)r0 * N + cc] = make_float2(c[mt][nt][0], c[mt][nt][1]);
            if (r0 + 8 < M)
                *(float2*)&C[(size_t)(r0 + 8) * N + cc] = make_float2(c[mt][nt][2], c[mt][nt][3]);
        }
    }
}

// ---------------- attention dots ----------------
__global__ void k_attdot1(const float* __restrict__ h, const float* __restrict__ as_,
                          const float* __restrict__ ad_, int n) {
    int nid = blockIdx.x;
    int t = threadIdx.x, w = t >> 5, lane = t & 31;
    float4 v = *(const float4*)&h[(size_t)nid * D1 + t * 4];
    float4 a = *(const float4*)&as_[t * 4];
    float4 b = *(const float4*)&ad_[t * 4];
    float ps = v.x * a.x + v.y * a.y + v.z * a.z + v.w * a.w;
    float pd = v.x * b.x + v.y * b.y + v.z * b.z + v.w * b.w;
#pragma unroll
    for (int o = 16; o > 0; o >>= 1) {
        ps += __shfl_xor_sync(0xffffffffu, ps, o);
        pd += __shfl_xor_sync(0xffffffffu, pd, o);
    }
    if (lane == 0) {
        g_asrc1[nid * HH + w] = ps;
        g_adst1[nid * HH + w] = pd;
    }
}

__global__ void k_attdot2(const float* __restrict__ h, const float* __restrict__ as_,
                          const float* __restrict__ ad_, int n) {
    int warp = (blockIdx.x * blockDim.x + threadIdx.x) >> 5;
    int lane = threadIdx.x & 31;
    if (warp >= n) return;
    const float* hr = h + (size_t)warp * CC2;
    float4 v0 = *(const float4*)&hr[lane * 8];
    float4 v1 = *(const float4*)&hr[lane * 8 + 4];
    float4 a0 = *(const float4*)&as_[lane * 8];
    float4 a1 = *(const float4*)&as_[lane * 8 + 4];
    float4 b0 = *(const float4*)&ad_[lane * 8];
    float4 b1 = *(const float4*)&ad_[lane * 8 + 4];
    float ps = v0.x * a0.x + v0.y * a0.y + v0.z * a0.z + v0.w * a0.w +
               v1.x * a1.x + v1.y * a1.y + v1.z * a1.z + v1.w * a1.w;
    float pd = v0.x * b0.x + v0.y * b0.y + v0.z * b0.z + v0.w * b0.w +
               v1.x * b1.x + v1.y * b1.y + v1.z * b1.z + v1.w * b1.w;
#pragma unroll
    for (int o = 16; o > 0; o >>= 1) {
        ps += __shfl_xor_sync(0xffffffffu, ps, o);
        pd += __shfl_xor_sync(0xffffffffu, pd, o);
    }
    if (lane == 0) {
        g_asrc2[warp] = ps;
        g_adst2[warp] = pd;
    }
}

// ---------------- fused softmax + aggregation ----------------
// Layer 1: block(128) per dst node; warp w = head w; thread t -> channels 4t..4t+3.
// Softmax without max-shift (logits bounded ~|1|): analytically identical.
__global__ void k_gat1_agg(const float* __restrict__ h, const float* __restrict__ bias,
                           float* __restrict__ out) {
    int d = blockIdx.x;
    int t = threadIdx.x, w = t >> 5, lane = t & 31;
    int beg = g_rowptr[d], end = g_rowptr[d + 1];
    float ad = g_adst1[d * HH + w];

    float sum = 0.f;
    for (int k = beg + lane; k < end; k += 32) {
        int s = g_col[k];
        float e = g_asrc1[s * HH + w] + ad;
        e = (e > 0.f) ? e : 0.2f * e;
        sum += __expf(e);
    }
#pragma unroll
    for (int o = 16; o > 0; o >>= 1) sum += __shfl_xor_sync(0xffffffffu, sum, o);
    float inv = 1.f / sum;

    float ax = 0.f, ay = 0.f, az = 0.f, aw = 0.f;
    for (int k = beg; k < end; k++) {
        int s = g_col[k];
        float e = g_asrc1[s * HH + w] + ad;
        e = (e > 0.f) ? e : 0.2f * e;
        float a = __expf(e) * inv;
        float4 hv = *(const float4*)&h[(size_t)s * D1 + t * 4];
        ax += hv.x * a; ay += hv.y * a; az += hv.z * a; aw += hv.w * a;
    }
    float4 b = *(const float4*)&bias[t * 4];
    *(float4*)&out[(size_t)d * D1 + t * 4] =
        make_float4(fmaxf(ax + b.x, 0.f), fmaxf(ay + b.y, 0.f),
                    fmaxf(az + b.z, 0.f), fmaxf(aw + b.w, 0.f));
}

// Layer 2: block(64) per dst node (2 warps, each computes the full edge-sum redundantly).
__global__ void k_gat2_agg(const float* __restrict__ h, const float* __restrict__ bias,
                           float* __restrict__ out) {
    int d = blockIdx.x;
    int t = threadIdx.x, lane = t & 31;
    int beg = g_rowptr[d], end = g_rowptr[d + 1];
    float ad = g_adst2[d];

    float sum = 0.f;
    for (int k = beg + lane; k < end; k += 32) {
        int s = g_col[k];
        float e = g_asrc2[s] + ad;
        e = (e > 0.f) ? e : 0.2f * e;
        sum += __expf(e);
    }
#pragma unroll
    for (int o = 16; o > 0; o >>= 1) sum += __shfl_xor_sync(0xffffffffu, sum, o);
    float inv = 1.f / sum;

    float ax = 0.f, ay = 0.f, az = 0.f, aw = 0.f;
    for (int k = beg; k < end; k++) {
        int s = g_col[k];
        float e = g_asrc2[s] + ad;
        e = (e > 0.f) ? e : 0.2f * e;
        float a = __expf(e) * inv;
        float4 hv = *(const float4*)&h[(size_t)s * CC2 + t * 4];
        ax += hv.x * a; ay += hv.y * a; az += hv.z * a; aw += hv.w * a;
    }
    float4 b = *(const float4*)&bias[t * 4];
    *(float4*)&out[(size_t)d * CC2 + t * 4] =
        make_float4(ax + b.x, ay + b.y, az + b.z, aw + b.w);
}

// ---------------- fused pool + MLP head ----------------
__global__ void k_poolhead(const float* __restrict__ x,
                           const float* __restrict__ w1, const float* __restrict__ b1,
                           const float* __restrict__ w2, const float* __restrict__ b2,
                           float* __restrict__ out) {
    int g = blockIdx.x;
    int t = threadIdx.x;  // 256
    __shared__ float pool[CC2];
    __shared__ float s1[64];
    __shared__ float logits[NCLS];

    int beg = g_starts[g], end = g_starts[g + 1];
    float m = -1e30f;
    for (int i = beg; i < end; i++) m = fmaxf(m, x[(size_t)i * CC2 + t]);
    pool[t] = m;
    __syncthreads();

    if (t < 64) {
        float acc = b1[t];
        for (int k = 0; k < CC2; k++) acc += pool[k] * w1[k * 64 + t];
        s1[t] = fmaxf(acc, 0.f);
    }
    __syncthreads();
    if (t < NCLS) {
        float l = b2[t];
        for (int k = 0; k < 64; k++) l += s1[k] * w2[k * NCLS + t];
        logits[t] = l;
    }
    __syncthreads();
    if (t < NCLS) {
        float mm = -1e30f;
        for (int j = 0; j < NCLS; j++) mm = fmaxf(mm, logits[j]);
        float se = 0.f;
        for (int j = 0; j < NCLS; j++) se += expf(logits[j] - mm);
        out[g * NCLS + t] = logits[t] - mm - logf(se);
    }
}

// ---------------- launch ----------------
extern "C" void kernel_launch(void* const* d_in, const int* in_sizes, int n_in,
                              void* d_out, int out_size) {
    const float* x        = (const float*)d_in[0];
    const int*   ei       = (const int*)d_in[1];
    const int*   batch    = (const int*)d_in[2];
    const float* W1       = (const float*)d_in[3];
    const float* att_src1 = (const float*)d_in[4];
    const float* att_dst1 = (const float*)d_in[5];
    const float* b1       = (const float*)d_in[6];
    const float* W2       = (const float*)d_in[7];
    const float* att_src2 = (const float*)d_in[8];
    const float* att_dst2 = (const float*)d_in[9];
    const float* b2       = (const float*)d_in[10];
    const float* fc1_w    = (const float*)d_in[11];
    const float* fc1_b    = (const float*)d_in[12];
    const float* fc2_w    = (const float*)d_in[13];
    const float* fc2_b    = (const float*)d_in[14];
    float* out = (float*)d_out;

    const int n = in_sizes[2];
    const int E = in_sizes[1] / 2;

    static int smem_set = 0;
    if (!smem_set) {
        cudaFuncSetAttribute(k_gemm_tf32, cudaFuncAttributeMaxDynamicSharedMemorySize,
                             GEMM_SMEM_BYTES);
        smem_set = 1;
    }

    float *h1, *out1, *h2, *out2;
    cudaGetSymbolAddress((void**)&h1, g_h1);
    cudaGetSymbolAddress((void**)&out1, g_out1);
    cudaGetSymbolAddress((void**)&h2, g_h2);
    cudaGetSymbolAddress((void**)&out2, g_out2);

    // ---- CSR build ----
    k_init<<<(n + 255) / 256, 256>>>(batch, n);
    k_count_deg<<<(E + 255) / 256, 256>>>(ei, E);
    int nb = (n + 1023) / 1024;
    k_scan_block<<<nb, 1024>>>(n);
    k_scan_bsums<<<1, 32>>>(nb, n);
    k_scan_add<<<(n + 255) / 256, 256>>>(n);
    k_scatter<<<(E + n + 255) / 256, 256>>>(ei, E, n);

    // ---- layer 1 ----
    {
        dim3 grid(D1 / TBN, (n + TBM - 1) / TBM);
        k_gemm_tf32<<<grid, 256, GEMM_SMEM_BYTES>>>(x, W1, h1, n, D1, FF);
    }
    k_attdot1<<<n, 128>>>(h1, att_src1, att_dst1, n);
    k_gat1_agg<<<n, 128>>>(h1, b1, out1);

    // ---- layer 2 ----
    {
        dim3 grid(CC2 / TBN, (n + TBM - 1) / TBM);
        k_gemm_tf32<<<grid, 256, GEMM_SMEM_BYTES>>>(out1, W2, h2, n, CC2, D1);
    }
    k_attdot2<<<(n * 32 + 255) / 256, 256>>>(h2, att_src2, att_dst2, n);
    k_gat2_agg<<<n, 64>>>(h2, b2, out2);

    // ---- pool + head ----
    k_poolhead<<<GG, CC2>>>(out2, fc1_w, fc1_b, fc2_w, fc2_b, out);
}

// round 5
// speedup vs baseline: 1.8721x; 1.0255x over previous
#include <cuda_runtime.h>
#include <cuda_bf16.h>
#include <math.h>
#include <stdint.h>

// ---------------- problem constants ----------------
#define NN      20000
#define EE      160000
#define ETOT    (2*EE + NN)
#define FF      128
#define HH      4
#define CC1     128
#define D1      (HH*CC1)       // 512
#define CC2     256
#define GG      64
#define NCLS    10

// ---------------- device scratch ----------------
__device__ __nv_bfloat16 g_h1[NN * D1];   // x @ W1 (bf16)
__device__ float         g_out1[NN * D1]; // relu(GAT1), fp32 (feeds GEMM2)
__device__ __nv_bfloat16 g_h2[NN * CC2];  // out1 @ W2 (bf16)
__device__ float         g_out2[NN * CC2];// GAT2 (fp32, feeds pool)
__device__ float g_asrc1[NN * HH];
__device__ float g_adst1[NN * HH];
__device__ float g_asrc2[NN];
__device__ float g_adst2[NN];
__device__ int   g_deg[NN];
__device__ int   g_rowptr[NN + 1];
__device__ int   g_wp[NN];
__device__ int   g_col[ETOT];
__device__ int   g_bsums[32];
__device__ int   g_starts[GG + 1];

// ---------------- CSR build ----------------
__global__ void k_init(const int* __restrict__ batch, int n) {
    int i = blockIdx.x * blockDim.x + threadIdx.x;
    if (i < n) {
        g_deg[i] = 1;  // self loop
        if (i == 0) {
            g_starts[batch[0]] = 0;
            g_starts[GG] = n;
        } else if (batch[i] != batch[i - 1]) {
            g_starts[batch[i]] = i;
        }
    }
}

__global__ void k_count_deg(const int* __restrict__ ei, int E) {
    int j = blockIdx.x * blockDim.x + threadIdx.x;
    if (j < E) {
        atomicAdd(&g_deg[ei[j]], 1);
        atomicAdd(&g_deg[ei[E + j]], 1);
    }
}

__global__ void k_scan_block(int n) {
    __shared__ int s[1024];
    int i = blockIdx.x * 1024 + threadIdx.x;
    int v = (i < n) ? g_deg[i] : 0;
    s[threadIdx.x] = v;
    __syncthreads();
    for (int off = 1; off < 1024; off <<= 1) {
        int x = (threadIdx.x >= off) ? s[threadIdx.x - off] : 0;
        __syncthreads();
        s[threadIdx.x] += x;
        __syncthreads();
    }
    if (i < n) g_rowptr[i] = s[threadIdx.x] - v;
    if (threadIdx.x == 1023) g_bsums[blockIdx.x] = s[1023];
}

__global__ void k_scan_bsums(int nb, int n) {
    int t = threadIdx.x;
    int v = (t < nb) ? g_bsums[t] : 0;
    int orig = v;
#pragma unroll
    for (int o = 1; o < 32; o <<= 1) {
        int x = __shfl_up_sync(0xffffffffu, v, o);
        if (t >= o) v += x;
    }
    if (t < nb) g_bsums[t] = v - orig;
    if (t == nb - 1) g_rowptr[n] = v;
}

__global__ void k_scan_add(int n) {
    int i = blockIdx.x * blockDim.x + threadIdx.x;
    if (i < n) {
        int v = g_rowptr[i] + g_bsums[i >> 10];
        g_rowptr[i] = v;
        g_wp[i] = v;
    }
}

__global__ void k_scatter(const int* __restrict__ ei, int E, int n) {
    int j = blockIdx.x * blockDim.x + threadIdx.x;
    if (j < E) {
        int s = ei[j], d = ei[E + j];
        g_col[atomicAdd(&g_wp[d], 1)] = s;
        g_col[atomicAdd(&g_wp[s], 1)] = d;
    } else if (j < E + n) {
        int i = j - E;
        g_col[atomicAdd(&g_wp[i], 1)] = i;
    }
}

// ---------------- tf32 tensor-core GEMM (cp.async 2-stage, bf16 output) ----------------
__device__ __forceinline__ void mma_tf32(float c[4], const unsigned a[4], const unsigned b[2]) {
    asm volatile(
        "mma.sync.aligned.m16n8k8.row.col.f32.tf32.tf32.f32 "
        "{%0,%1,%2,%3}, {%4,%5,%6,%7}, {%8,%9}, {%0,%1,%2,%3};"
        : "+f"(c[0]), "+f"(c[1]), "+f"(c[2]), "+f"(c[3])
        : "r"(a[0]), "r"(a[1]), "r"(a[2]), "r"(a[3]), "r"(b[0]), "r"(b[1]));
}

__device__ __forceinline__ void cp16(uint32_t dst, const float* src, int szbytes) {
    asm volatile("cp.async.ca.shared.global [%0], [%1], 16, %2;\n"
                 :: "r"(dst), "l"(src), "r"(szbytes));
}

#define TBM 128
#define TBN 128
#define TBK 32
#define AS_STRIDE (TBK + 4)
#define BS_STRIDE (TBN + 4)
#define AS_SIZE (TBM * AS_STRIDE)
#define BS_SIZE (TBK * BS_STRIDE)
#define GEMM_SMEM_BYTES (2 * (AS_SIZE + BS_SIZE) * 4)  // 70656

__global__ __launch_bounds__(256) void k_gemm_tf32_bf16out(const float* __restrict__ A,
                                                           const float* __restrict__ B,
                                                           __nv_bfloat16* __restrict__ C,
                                                           int M, int N, int K) {
    extern __shared__ float sm_[];
    float* As = sm_;
    float* Bs = sm_ + 2 * AS_SIZE;
    uint32_t as_base = (uint32_t)__cvta_generic_to_shared(As);
    uint32_t bs_base = (uint32_t)__cvta_generic_to_shared(Bs);

    int tid = threadIdx.x;
    int bm = blockIdx.y * TBM, bn = blockIdx.x * TBN;
    int w = tid >> 5, lane = tid & 31;
    int wy = w & 3, wx = w >> 2;
    int gid = lane >> 2, tig = lane & 3;

    float c[2][8][4];
#pragma unroll
    for (int mt = 0; mt < 2; mt++)
#pragma unroll
        for (int nt = 0; nt < 8; nt++)
#pragma unroll
            for (int r = 0; r < 4; r++) c[mt][nt][r] = 0.f;

    const int KT = K / TBK;

    auto load_tile = [&](int k0, int st) {
#pragma unroll
        for (int i = 0; i < 4; i++) {
            int q = tid + i * 256;
            int row = q >> 3;
            int kk = (q & 7) << 2;
            int gr = bm + row;
            uint32_t d = as_base + (uint32_t)(st * AS_SIZE + row * AS_STRIDE + kk) * 4u;
            cp16(d, &A[(size_t)gr * K + k0 + kk], (gr < M) ? 16 : 0);
        }
#pragma unroll
        for (int i = 0; i < 4; i++) {
            int q = tid + i * 256;
            int kr = q >> 5;
            int nc = (q & 31) << 2;
            uint32_t d = bs_base + (uint32_t)(st * BS_SIZE + kr * BS_STRIDE + nc) * 4u;
            cp16(d, &B[(size_t)(k0 + kr) * N + bn + nc], 16);
        }
        asm volatile("cp.async.commit_group;\n");
    };

    load_tile(0, 0);

    for (int it = 0; it < KT; it++) {
        if (it + 1 < KT) {
            load_tile((it + 1) * TBK, (it + 1) & 1);
            asm volatile("cp.async.wait_group 1;\n");
        } else {
            asm volatile("cp.async.wait_group 0;\n");
        }
        __syncthreads();

        const float* as = As + (it & 1) * AS_SIZE;
        const float* bsm = Bs + (it & 1) * BS_SIZE;
#pragma unroll
        for (int ks = 0; ks < 4; ks++) {
            int kb = ks * 8;
            unsigned af[2][4], bf[8][2];
#pragma unroll
            for (int mt = 0; mt < 2; mt++) {
                int r0 = wy * 32 + mt * 16;
                af[mt][0] = __float_as_uint(as[(r0 + gid) * AS_STRIDE + kb + tig]);
                af[mt][1] = __float_as_uint(as[(r0 + gid + 8) * AS_STRIDE + kb + tig]);
                af[mt][2] = __float_as_uint(as[(r0 + gid) * AS_STRIDE + kb + tig + 4]);
                af[mt][3] = __float_as_uint(as[(r0 + gid + 8) * AS_STRIDE + kb + tig + 4]);
            }
#pragma unroll
            for (int nt = 0; nt < 8; nt++) {
                int c0 = wx * 64 + nt * 8;
                bf[nt][0] = __float_as_uint(bsm[(kb + tig) * BS_STRIDE + c0 + gid]);
                bf[nt][1] = __float_as_uint(bsm[(kb + tig + 4) * BS_STRIDE + c0 + gid]);
            }
#pragma unroll
            for (int mt = 0; mt < 2; mt++)
#pragma unroll
                for (int nt = 0; nt < 8; nt++) mma_tf32(c[mt][nt], af[mt], bf[nt]);
        }
        __syncthreads();
    }

#pragma unroll
    for (int mt = 0; mt < 2; mt++) {
        int r0 = bm + wy * 32 + mt * 16 + gid;
#pragma unroll
        for (int nt = 0; nt < 8; nt++) {
            int cc = bn + wx * 64 + nt * 8 + 2 * tig;
            if (r0 < M) {
                __nv_bfloat162 v = __float22bfloat162_rn(make_float2(c[mt][nt][0], c[mt][nt][1]));
                *(__nv_bfloat162*)&C[(size_t)r0 * N + cc] = v;
            }
            if (r0 + 8 < M) {
                __nv_bfloat162 v = __float22bfloat162_rn(make_float2(c[mt][nt][2], c[mt][nt][3]));
                *(__nv_bfloat162*)&C[(size_t)(r0 + 8) * N + cc] = v;
            }
        }
    }
}

// ---------------- attention dots (bf16 h) ----------------
__global__ void k_attdot1(const __nv_bfloat16* __restrict__ h, const float* __restrict__ as_,
                          const float* __restrict__ ad_, int n) {
    int nid = blockIdx.x;
    int t = threadIdx.x, w = t >> 5, lane = t & 31;
    uint2 raw = *(const uint2*)(h + (size_t)nid * D1 + t * 4);
    float2 f0 = __bfloat1622float2(*reinterpret_cast<__nv_bfloat162*>(&raw.x));
    float2 f1 = __bfloat1622float2(*reinterpret_cast<__nv_bfloat162*>(&raw.y));
    float4 a = *(const float4*)&as_[t * 4];
    float4 b = *(const float4*)&ad_[t * 4];
    float ps = f0.x * a.x + f0.y * a.y + f1.x * a.z + f1.y * a.w;
    float pd = f0.x * b.x + f0.y * b.y + f1.x * b.z + f1.y * b.w;
#pragma unroll
    for (int o = 16; o > 0; o >>= 1) {
        ps += __shfl_xor_sync(0xffffffffu, ps, o);
        pd += __shfl_xor_sync(0xffffffffu, pd, o);
    }
    if (lane == 0) {
        g_asrc1[nid * HH + w] = ps;
        g_adst1[nid * HH + w] = pd;
    }
}

__global__ void k_attdot2(const __nv_bfloat16* __restrict__ h, const float* __restrict__ as_,
                          const float* __restrict__ ad_, int n) {
    int warp = (blockIdx.x * blockDim.x + threadIdx.x) >> 5;
    int lane = threadIdx.x & 31;
    if (warp >= n) return;
    uint4 raw = *(const uint4*)(h + (size_t)warp * CC2 + lane * 8);
    float2 f0 = __bfloat1622float2(*reinterpret_cast<__nv_bfloat162*>(&raw.x));
    float2 f1 = __bfloat1622float2(*reinterpret_cast<__nv_bfloat162*>(&raw.y));
    float2 f2 = __bfloat1622float2(*reinterpret_cast<__nv_bfloat162*>(&raw.z));
    float2 f3 = __bfloat1622float2(*reinterpret_cast<__nv_bfloat162*>(&raw.w));
    float4 a0 = *(const float4*)&as_[lane * 8];
    float4 a1 = *(const float4*)&as_[lane * 8 + 4];
    float4 b0 = *(const float4*)&ad_[lane * 8];
    float4 b1 = *(const float4*)&ad_[lane * 8 + 4];
    float ps = f0.x * a0.x + f0.y * a0.y + f1.x * a0.z + f1.y * a0.w +
               f2.x * a1.x + f2.y * a1.y + f3.x * a1.z + f3.y * a1.w;
    float pd = f0.x * b0.x + f0.y * b0.y + f1.x * b0.z + f1.y * b0.w +
               f2.x * b1.x + f2.y * b1.y + f3.x * b1.z + f3.y * b1.w;
#pragma unroll
    for (int o = 16; o > 0; o >>= 1) {
        ps += __shfl_xor_sync(0xffffffffu, ps, o);
        pd += __shfl_xor_sync(0xffffffffu, pd, o);
    }
    if (lane == 0) {
        g_asrc2[warp] = ps;
        g_adst2[warp] = pd;
    }
}

// ---------------- fused softmax + aggregation (bf16 h gather) ----------------
__global__ void k_gat1_agg(const __nv_bfloat16* __restrict__ h, const float* __restrict__ bias,
                           float* __restrict__ out) {
    int d = blockIdx.x;
    int t = threadIdx.x, w = t >> 5, lane = t & 31;
    int beg = g_rowptr[d], end = g_rowptr[d + 1];
    float ad = g_adst1[d * HH + w];

    float sum = 0.f;
    for (int k = beg + lane; k < end; k += 32) {
        int s = g_col[k];
        float e = g_asrc1[s * HH + w] + ad;
        e = (e > 0.f) ? e : 0.2f * e;
        sum += __expf(e);
    }
#pragma unroll
    for (int o = 16; o > 0; o >>= 1) sum += __shfl_xor_sync(0xffffffffu, sum, o);
    float inv = 1.f / sum;

    float ax = 0.f, ay = 0.f, az = 0.f, aw = 0.f;
    for (int k = beg; k < end; k++) {
        int s = g_col[k];
        float e = g_asrc1[s * HH + w] + ad;
        e = (e > 0.f) ? e : 0.2f * e;
        float a = __expf(e) * inv;
        uint2 raw = *(const uint2*)(h + (size_t)s * D1 + t * 4);
        float2 f0 = __bfloat1622float2(*reinterpret_cast<__nv_bfloat162*>(&raw.x));
        float2 f1 = __bfloat1622float2(*reinterpret_cast<__nv_bfloat162*>(&raw.y));
        ax += f0.x * a; ay += f0.y * a; az += f1.x * a; aw += f1.y * a;
    }
    float4 b = *(const float4*)&bias[t * 4];
    *(float4*)&out[(size_t)d * D1 + t * 4] =
        make_float4(fmaxf(ax + b.x, 0.f), fmaxf(ay + b.y, 0.f),
                    fmaxf(az + b.z, 0.f), fmaxf(aw + b.w, 0.f));
}

__global__ void k_gat2_agg(const __nv_bfloat16* __restrict__ h, const float* __restrict__ bias,
                           float* __restrict__ out) {
    int d = blockIdx.x;
    int t = threadIdx.x, lane = t & 31;
    int beg = g_rowptr[d], end = g_rowptr[d + 1];
    float ad = g_adst2[d];

    float sum = 0.f;
    for (int k = beg + lane; k < end; k += 32) {
        int s = g_col[k];
        float e = g_asrc2[s] + ad;
        e = (e > 0.f) ? e : 0.2f * e;
        sum += __expf(e);
    }
#pragma unroll
    for (int o = 16; o > 0; o >>= 1) sum += __shfl_xor_sync(0xffffffffu, sum, o);
    float inv = 1.f / sum;

    float ax = 0.f, ay = 0.f, az = 0.f, aw = 0.f;
    for (int k = beg; k < end; k++) {
        int s = g_col[k];
        float e = g_asrc2[s] + ad;
        e = (e > 0.f) ? e : 0.2f * e;
        float a = __expf(e) * inv;
        uint2 raw = *(const uint2*)(h + (size_t)s * CC2 + t * 4);
        float2 f0 = __bfloat1622float2(*reinterpret_cast<__nv_bfloat162*>(&raw.x));
        float2 f1 = __bfloat1622float2(*reinterpret_cast<__nv_bfloat162*>(&raw.y));
        ax += f0.x * a; ay += f0.y * a; az += f1.x * a; aw += f1.y * a;
    }
    float4 b = *(const float4*)&bias[t * 4];
    *(float4*)&out[(size_t)d * CC2 + t * 4] =
        make_float4(ax + b.x, ay + b.y, az + b.z, aw + b.w);
}

// ---------------- fused pool + MLP head ----------------
__global__ void k_poolhead(const float* __restrict__ x,
                           const float* __restrict__ w1, const float* __restrict__ b1,
                           const float* __restrict__ w2, const float* __restrict__ b2,
                           float* __restrict__ out) {
    int g = blockIdx.x;
    int t = threadIdx.x;  // 256
    __shared__ float pool[CC2];
    __shared__ float s1[64];
    __shared__ float logits[NCLS];

    int beg = g_starts[g], end = g_starts[g + 1];
    float m = -1e30f;
    for (int i = beg; i < end; i++) m = fmaxf(m, x[(size_t)i * CC2 + t]);
    pool[t] = m;
    __syncthreads();

    if (t < 64) {
        float acc = b1[t];
        for (int k = 0; k < CC2; k++) acc += pool[k] * w1[k * 64 + t];
        s1[t] = fmaxf(acc, 0.f);
    }
    __syncthreads();
    if (t < NCLS) {
        float l = b2[t];
        for (int k = 0; k < 64; k++) l += s1[k] * w2[k * NCLS + t];
        logits[t] = l;
    }
    __syncthreads();
    if (t < NCLS) {
        float mm = -1e30f;
        for (int j = 0; j < NCLS; j++) mm = fmaxf(mm, logits[j]);
        float se = 0.f;
        for (int j = 0; j < NCLS; j++) se += expf(logits[j] - mm);
        out[g * NCLS + t] = logits[t] - mm - logf(se);
    }
}

// ---------------- launch ----------------
extern "C" void kernel_launch(void* const* d_in, const int* in_sizes, int n_in,
                              void* d_out, int out_size) {
    const float* x        = (const float*)d_in[0];
    const int*   ei       = (const int*)d_in[1];
    const int*   batch    = (const int*)d_in[2];
    const float* W1       = (const float*)d_in[3];
    const float* att_src1 = (const float*)d_in[4];
    const float* att_dst1 = (const float*)d_in[5];
    const float* b1       = (const float*)d_in[6];
    const float* W2       = (const float*)d_in[7];
    const float* att_src2 = (const float*)d_in[8];
    const float* att_dst2 = (const float*)d_in[9];
    const float* b2       = (const float*)d_in[10];
    const float* fc1_w    = (const float*)d_in[11];
    const float* fc1_b    = (const float*)d_in[12];
    const float* fc2_w    = (const float*)d_in[13];
    const float* fc2_b    = (const float*)d_in[14];
    float* out = (float*)d_out;

    const int n = in_sizes[2];
    const int E = in_sizes[1] / 2;

    static int smem_set = 0;
    if (!smem_set) {
        cudaFuncSetAttribute(k_gemm_tf32_bf16out, cudaFuncAttributeMaxDynamicSharedMemorySize,
                             GEMM_SMEM_BYTES);
        smem_set = 1;
    }

    __nv_bfloat16 *h1, *h2;
    float *out1, *out2;
    cudaGetSymbolAddress((void**)&h1, g_h1);
    cudaGetSymbolAddress((void**)&out1, g_out1);
    cudaGetSymbolAddress((void**)&h2, g_h2);
    cudaGetSymbolAddress((void**)&out2, g_out2);

    // ---- CSR build ----
    k_init<<<(n + 255) / 256, 256>>>(batch, n);
    k_count_deg<<<(E + 255) / 256, 256>>>(ei, E);
    int nb = (n + 1023) / 1024;
    k_scan_block<<<nb, 1024>>>(n);
    k_scan_bsums<<<1, 32>>>(nb, n);
    k_scan_add<<<(n + 255) / 256, 256>>>(n);
    k_scatter<<<(E + n + 255) / 256, 256>>>(ei, E, n);

    // ---- layer 1 ----
    {
        dim3 grid(D1 / TBN, (n + TBM - 1) / TBM);
        k_gemm_tf32_bf16out<<<grid, 256, GEMM_SMEM_BYTES>>>(x, W1, h1, n, D1, FF);
    }
    k_attdot1<<<n, 128>>>(h1, att_src1, att_dst1, n);
    k_gat1_agg<<<n, 128>>>(h1, b1, out1);

    // ---- layer 2 ----
    {
        dim3 grid(CC2 / TBN, (n + TBM - 1) / TBM);
        k_gemm_tf32_bf16out<<<grid, 256, GEMM_SMEM_BYTES>>>(out1, W2, h2, n, CC2, D1);
    }
    k_attdot2<<<(n * 32 + 255) / 256, 256>>>(h2, att_src2, att_dst2, n);
    k_gat2_agg<<<n, 64>>>(h2, b2, out2);

    // ---- pool + head ----
    k_poolhead<<<GG, CC2>>>(out2, fc1_w, fc1_b, fc2_w, fc2_b, out);
}